// round 3
// baseline (speedup 1.0000x reference)
#include <cuda_runtime.h>
#include <cstdint>

#define D_FEAT    64
#define MAX_NODES 50000
#define MAX_EDGES 800000

// Scratch (__device__ globals — no allocation allowed).
static __device__ float g_y[(size_t)MAX_NODES * D_FEAT];  // relu(x W + b)
static __device__ int   g_cnt[MAX_NODES];                 // per-dst degree
static __device__ int   g_rowptr[MAX_NODES + 1];          // CSR row pointers
static __device__ int   g_offs[MAX_NODES];                // running fill offsets
static __device__ int   g_col[MAX_EDGES];                 // src per (dst-sorted) edge
static __device__ int   g_is64;                           // edge_index dtype flag

// ---------------------------------------------------------------------------
// Detect index dtype: int64 indices < 2^31 have all-odd-word == 0.
// ---------------------------------------------------------------------------
__global__ void detect_kernel(const int* __restrict__ ei_words) {
    __shared__ int any_nonzero;
    if (threadIdx.x == 0) any_nonzero = 0;
    __syncthreads();
    if (ei_words[2 * threadIdx.x + 1] != 0) atomicOr(&any_nonzero, 1);
    __syncthreads();
    if (threadIdx.x == 0) g_is64 = any_nonzero ? 0 : 1;
}

__device__ __forceinline__ int load_idx(const void* ei, size_t i) {
    return g_is64 ? (int)__ldg(&((const long long*)ei)[i])
                  : __ldg(&((const int*)ei)[i]);
}

// ---------------------------------------------------------------------------
// Per-node MLP: y = relu(x @ W + b).  256 thr / 64 rows per block.
// ---------------------------------------------------------------------------
__global__ __launch_bounds__(256) void mlp_kernel(const float* __restrict__ x,
                                                  const float* __restrict__ W,
                                                  const float* __restrict__ b,
                                                  int n) {
    __shared__ float sW[64 * 64];   // [k][c]
    __shared__ float sx[64 * 68];   // [r][k], padded stride

    const int tid  = threadIdx.x;
    const int row0 = blockIdx.x * 64;

    {
        const float4* W4  = (const float4*)W;
        float4*       sW4 = (float4*)sW;
#pragma unroll
        for (int i = 0; i < 4; i++) sW4[tid + 256 * i] = W4[tid + 256 * i];
    }
#pragma unroll
    for (int i = 0; i < 4; i++) {
        int idx = tid + 256 * i;
        int r   = idx >> 4;
        int kk  = idx & 15;
        float4 v = make_float4(0.f, 0.f, 0.f, 0.f);
        if (row0 + r < n)
            v = ((const float4*)(x + (size_t)(row0 + r) * D_FEAT))[kk];
        *(float4*)&sx[r * 68 + kk * 4] = v;
    }
    __syncthreads();

    const int c4 = tid & 15;
    const int r0 = tid >> 4;

    float4 acc[4];
#pragma unroll
    for (int j = 0; j < 4; j++) acc[j] = make_float4(0.f, 0.f, 0.f, 0.f);

#pragma unroll 8
    for (int k = 0; k < 64; k++) {
        float4 w = *(const float4*)&sW[k * 64 + c4 * 4];
#pragma unroll
        for (int j = 0; j < 4; j++) {
            float xv = sx[(r0 + 16 * j) * 68 + k];
            acc[j].x += xv * w.x;
            acc[j].y += xv * w.y;
            acc[j].z += xv * w.z;
            acc[j].w += xv * w.w;
        }
    }

    float4 bb = ((const float4*)b)[c4];
#pragma unroll
    for (int j = 0; j < 4; j++) {
        int r = row0 + r0 + 16 * j;
        if (r < n) {
            float4 v;
            v.x = fmaxf(acc[j].x + bb.x, 0.f);
            v.y = fmaxf(acc[j].y + bb.y, 0.f);
            v.z = fmaxf(acc[j].z + bb.z, 0.f);
            v.w = fmaxf(acc[j].w + bb.w, 0.f);
            ((float4*)(g_y + (size_t)r * D_FEAT))[c4] = v;
        }
    }
}

// ---------------------------------------------------------------------------
// Counting sort by dst: zero -> histogram -> scan -> fill.
// ---------------------------------------------------------------------------
__global__ void zerocnt_kernel(int n) {
    int i = blockIdx.x * blockDim.x + threadIdx.x;
    if (i < n) g_cnt[i] = 0;
}

__global__ void hist_kernel(const void* __restrict__ ei, int E) {
    int e = blockIdx.x * blockDim.x + threadIdx.x;
    if (e >= E) return;
    int dst = load_idx(ei, (size_t)E + e);
    atomicAdd(&g_cnt[dst], 1);
}

// Single-block exclusive scan over n bins (n <= 1024 * BPT).
__global__ __launch_bounds__(1024) void scan_kernel(int n) {
    __shared__ int ssum[1024];
    const int t   = threadIdx.x;
    const int bpt = (n + 1023) >> 10;
    const int lo  = t * bpt;
    const int hi  = min(lo + bpt, n);

    int s = 0;
    for (int i = lo; i < hi; i++) s += g_cnt[i];
    ssum[t] = s;
    __syncthreads();

    // Hillis-Steele inclusive scan over 1024 partials.
#pragma unroll
    for (int d = 1; d < 1024; d <<= 1) {
        int w = (t >= d) ? ssum[t - d] : 0;
        __syncthreads();
        ssum[t] += w;
        __syncthreads();
    }

    int run = ssum[t] - s;  // exclusive prefix of this thread's span
    for (int i = lo; i < hi; i++) {
        int c = g_cnt[i];
        g_rowptr[i] = run;
        g_offs[i]   = run;
        run += c;
    }
    if (t == 1023) g_rowptr[n] = ssum[1023];
}

__global__ void fill_kernel(const void* __restrict__ ei, int E) {
    int e = blockIdx.x * blockDim.x + threadIdx.x;
    if (e >= E) return;
    int src = load_idx(ei, e);
    int dst = load_idx(ei, (size_t)E + e);
    int pos = atomicAdd(&g_offs[dst], 1);
    g_col[pos] = src;
}

// ---------------------------------------------------------------------------
// Aggregate: one warp per node. Lane owns float2 slice (feats 2l, 2l+1).
// Pure gather + register accumulate + one coalesced store. No atomics.
// ---------------------------------------------------------------------------
__global__ __launch_bounds__(256) void agg_kernel(float* __restrict__ out, int n) {
    int warp = (blockIdx.x * blockDim.x + threadIdx.x) >> 5;
    int lane = threadIdx.x & 31;
    if (warp >= n) return;

    int beg = g_rowptr[warp];
    int end = g_rowptr[warp + 1];

    const float2* yb = (const float2*)g_y;
    float2 acc = make_float2(0.f, 0.f);

    int k = beg;
    for (; k + 1 < end; k += 2) {
        int s0 = __ldg(&g_col[k]);
        int s1 = __ldg(&g_col[k + 1]);
        float2 a = __ldg(yb + (size_t)s0 * 32 + lane);
        float2 c = __ldg(yb + (size_t)s1 * 32 + lane);
        acc.x += a.x + c.x;
        acc.y += a.y + c.y;
    }
    if (k < end) {
        int s = __ldg(&g_col[k]);
        float2 a = __ldg(yb + (size_t)s * 32 + lane);
        acc.x += a.x;
        acc.y += a.y;
    }

    ((float2*)out)[(size_t)warp * 32 + lane] = acc;
}

// ---------------------------------------------------------------------------
// Inputs: x [n*64 f32], edge_index [2*E int32/int64], W [64*64 f32], b [64].
// ---------------------------------------------------------------------------
extern "C" void kernel_launch(void* const* d_in, const int* in_sizes, int n_in,
                              void* d_out, int out_size) {
    const float* x   = (const float*)d_in[0];
    const void*  ei  = d_in[1];
    const float* W   = (const float*)d_in[2];
    const float* b   = (const float*)d_in[3];
    float*       out = (float*)d_out;

    int n = in_sizes[0] / D_FEAT;
    int E = in_sizes[1] / 2;

    detect_kernel<<<1, 256>>>((const int*)ei);
    mlp_kernel<<<(n + 63) / 64, 256>>>(x, W, b, n);

    zerocnt_kernel<<<(n + 255) / 256, 256>>>(n);
    hist_kernel<<<(E + 255) / 256, 256>>>(ei, E);
    scan_kernel<<<1, 1024>>>(n);
    fill_kernel<<<(E + 255) / 256, 256>>>(ei, E);

    int warps_needed = n;
    int grid = (warps_needed * 32 + 255) / 256;
    agg_kernel<<<grid, 256>>>(out, n);
}

// round 5
// speedup vs baseline: 1.0123x; 1.0123x over previous
#include <cuda_runtime.h>
#include <cstdint>

#define D_FEAT    64
#define MAX_NODES 50000
#define MAX_EDGES 800000

// Scratch (__device__ globals — no allocation allowed).
static __device__ float g_y[(size_t)MAX_NODES * D_FEAT];  // relu(x W + b)
static __device__ int2  g_edge[MAX_EDGES];                // packed (src, dst)
static __device__ int   g_is64;                           // edge_index dtype flag

// ---------------------------------------------------------------------------
// Detect index dtype: int64 indices < 2^31 have every odd 32-bit word == 0.
// ---------------------------------------------------------------------------
__global__ void detect_kernel(const int* __restrict__ ei_words) {
    __shared__ int any_nonzero;
    if (threadIdx.x == 0) any_nonzero = 0;
    __syncthreads();
    if (ei_words[2 * threadIdx.x + 1] != 0) atomicOr(&any_nonzero, 1);
    __syncthreads();
    if (threadIdx.x == 0) g_is64 = any_nonzero ? 0 : 1;
}

// ---------------------------------------------------------------------------
// Convert edge_index (int32 or int64, [2, E]) into packed int2 (src, dst).
// ---------------------------------------------------------------------------
__global__ __launch_bounds__(256) void prep_kernel(const void* __restrict__ ei, int E) {
    int e = blockIdx.x * blockDim.x + threadIdx.x;
    if (e >= E) return;
    int src, dst;
    if (g_is64) {
        const long long* p = (const long long*)ei;
        src = (int)__ldg(&p[e]);
        dst = (int)__ldg(&p[(size_t)E + e]);
    } else {
        const int* p = (const int*)ei;
        src = __ldg(&p[e]);
        dst = __ldg(&p[(size_t)E + e]);
    }
    g_edge[e] = make_int2(src, dst);
}

// ---------------------------------------------------------------------------
// Zero the output buffer (harness poisons it to 0xAA).
// ---------------------------------------------------------------------------
__global__ void zero_kernel(float4* __restrict__ out, int n4) {
    int i = blockIdx.x * blockDim.x + threadIdx.x;
    if (i < n4) out[i] = make_float4(0.f, 0.f, 0.f, 0.f);
}

// ---------------------------------------------------------------------------
// Per-node MLP: y = relu(x @ W + b).  256 thr / 64 rows per block.
// ---------------------------------------------------------------------------
__global__ __launch_bounds__(256) void mlp_kernel(const float* __restrict__ x,
                                                  const float* __restrict__ W,
                                                  const float* __restrict__ b,
                                                  int n) {
    __shared__ float sW[64 * 64];   // [k][c]
    __shared__ float sx[64 * 68];   // [r][k], padded stride

    const int tid  = threadIdx.x;
    const int row0 = blockIdx.x * 64;

    {
        const float4* W4  = (const float4*)W;
        float4*       sW4 = (float4*)sW;
#pragma unroll
        for (int i = 0; i < 4; i++) sW4[tid + 256 * i] = W4[tid + 256 * i];
    }
#pragma unroll
    for (int i = 0; i < 4; i++) {
        int idx = tid + 256 * i;
        int r   = idx >> 4;
        int kk  = idx & 15;
        float4 v = make_float4(0.f, 0.f, 0.f, 0.f);
        if (row0 + r < n)
            v = ((const float4*)(x + (size_t)(row0 + r) * D_FEAT))[kk];
        *(float4*)&sx[r * 68 + kk * 4] = v;
    }
    __syncthreads();

    const int c4 = tid & 15;
    const int r0 = tid >> 4;

    float4 acc[4];
#pragma unroll
    for (int j = 0; j < 4; j++) acc[j] = make_float4(0.f, 0.f, 0.f, 0.f);

#pragma unroll 8
    for (int k = 0; k < 64; k++) {
        float4 w = *(const float4*)&sW[k * 64 + c4 * 4];
#pragma unroll
        for (int j = 0; j < 4; j++) {
            float xv = sx[(r0 + 16 * j) * 68 + k];
            acc[j].x += xv * w.x;
            acc[j].y += xv * w.y;
            acc[j].z += xv * w.z;
            acc[j].w += xv * w.w;
        }
    }

    float4 bb = ((const float4*)b)[c4];
#pragma unroll
    for (int j = 0; j < 4; j++) {
        int r = row0 + r0 + 16 * j;
        if (r < n) {
            float4 v;
            v.x = fmaxf(acc[j].x + bb.x, 0.f);
            v.y = fmaxf(acc[j].y + bb.y, 0.f);
            v.z = fmaxf(acc[j].z + bb.z, 0.f);
            v.w = fmaxf(acc[j].w + bb.w, 0.f);
            ((float4*)(g_y + (size_t)r * D_FEAT))[c4] = v;
        }
    }
}

// ---------------------------------------------------------------------------
// Edge scatter: out[dst] += y[src].  4 threads/edge; each thread gathers 4
// independent float4 (MLP=4) and issues 4 vectorized REDs. Single LDG.64
// fetches both indices.
// ---------------------------------------------------------------------------
__global__ __launch_bounds__(256) void scatter_kernel(float* __restrict__ out, int E) {
    int t = blockIdx.x * blockDim.x + threadIdx.x;
    int e = t >> 2;
    if (e >= E) return;
    int q = t & 3;                  // quarter-row: 16 floats

    int2 ed = __ldg(&g_edge[e]);

    const float4* yr = (const float4*)(g_y + (size_t)ed.x * D_FEAT) + q * 4;
    float4 a0 = __ldg(yr + 0);
    float4 a1 = __ldg(yr + 1);
    float4 a2 = __ldg(yr + 2);
    float4 a3 = __ldg(yr + 3);

    float* o = out + (size_t)ed.y * D_FEAT + (q << 4);
    asm volatile("red.global.add.v4.f32 [%0], {%1, %2, %3, %4};"
                 :: "l"(o +  0), "f"(a0.x), "f"(a0.y), "f"(a0.z), "f"(a0.w) : "memory");
    asm volatile("red.global.add.v4.f32 [%0], {%1, %2, %3, %4};"
                 :: "l"(o +  4), "f"(a1.x), "f"(a1.y), "f"(a1.z), "f"(a1.w) : "memory");
    asm volatile("red.global.add.v4.f32 [%0], {%1, %2, %3, %4};"
                 :: "l"(o +  8), "f"(a2.x), "f"(a2.y), "f"(a2.z), "f"(a2.w) : "memory");
    asm volatile("red.global.add.v4.f32 [%0], {%1, %2, %3, %4};"
                 :: "l"(o + 12), "f"(a3.x), "f"(a3.y), "f"(a3.z), "f"(a3.w) : "memory");
}

// ---------------------------------------------------------------------------
// Inputs: x [n*64 f32], edge_index [2*E int32/int64], W [64*64 f32], b [64].
// ---------------------------------------------------------------------------
extern "C" void kernel_launch(void* const* d_in, const int* in_sizes, int n_in,
                              void* d_out, int out_size) {
    const float* x   = (const float*)d_in[0];
    const void*  ei  = d_in[1];
    const float* W   = (const float*)d_in[2];
    const float* b   = (const float*)d_in[3];
    float*       out = (float*)d_out;

    int n = in_sizes[0] / D_FEAT;
    int E = in_sizes[1] / 2;

    detect_kernel<<<1, 256>>>((const int*)ei);
    prep_kernel<<<(E + 255) / 256, 256>>>(ei, E);

    int n4 = out_size / 4;
    zero_kernel<<<(n4 + 255) / 256, 256>>>((float4*)d_out, n4);
    mlp_kernel<<<(n + 63) / 64, 256>>>(x, W, b, n);

    long long total = (long long)E * 4;
    int grid = (int)((total + 255) / 256);
    scatter_kernel<<<grid, 256>>>(out, E);
}

// round 8
// speedup vs baseline: 2.1978x; 2.1710x over previous
#include <cuda_runtime.h>
#include <cstdint>

#define D_FEAT    64
#define MAX_NODES 50000
#define MAX_EDGES 800000

// Scratch (__device__ globals — no allocation allowed).
static __device__ float g_y[(size_t)MAX_NODES * D_FEAT];  // relu(x W + b)
static __device__ int2  g_edge[MAX_EDGES];                // packed (src, dst)
static __device__ int   g_is64;                           // edge_index dtype flag

// ---------------------------------------------------------------------------
// Detect index dtype: int64 indices < 2^31 have every odd 32-bit word == 0.
// ---------------------------------------------------------------------------
__global__ void detect_kernel(const int* __restrict__ ei_words) {
    __shared__ int any_nonzero;
    if (threadIdx.x == 0) any_nonzero = 0;
    __syncthreads();
    if (ei_words[2 * threadIdx.x + 1] != 0) atomicOr(&any_nonzero, 1);
    __syncthreads();
    if (threadIdx.x == 0) g_is64 = any_nonzero ? 0 : 1;
}

// ---------------------------------------------------------------------------
// Convert edge_index (int32 or int64, [2, E]) into packed int2 (src, dst).
// ---------------------------------------------------------------------------
__global__ __launch_bounds__(256) void prep_kernel(const void* __restrict__ ei, int E) {
    int e = blockIdx.x * blockDim.x + threadIdx.x;
    if (e >= E) return;
    int src, dst;
    if (g_is64) {
        const long long* p = (const long long*)ei;
        src = (int)__ldg(&p[e]);
        dst = (int)__ldg(&p[(size_t)E + e]);
    } else {
        const int* p = (const int*)ei;
        src = __ldg(&p[e]);
        dst = __ldg(&p[(size_t)E + e]);
    }
    g_edge[e] = make_int2(src, dst);
}

// ---------------------------------------------------------------------------
// Zero the output buffer (harness poisons it to 0xAA).
// ---------------------------------------------------------------------------
__global__ void zero_kernel(float4* __restrict__ out, int n4) {
    int i = blockIdx.x * blockDim.x + threadIdx.x;
    if (i < n4) out[i] = make_float4(0.f, 0.f, 0.f, 0.f);
}

// ---------------------------------------------------------------------------
// Per-node MLP: y = relu(x @ W + b).  256 thr / 64 rows per block.
// ---------------------------------------------------------------------------
__global__ __launch_bounds__(256) void mlp_kernel(const float* __restrict__ x,
                                                  const float* __restrict__ W,
                                                  const float* __restrict__ b,
                                                  int n) {
    __shared__ float sW[64 * 64];   // [k][c]
    __shared__ float sx[64 * 68];   // [r][k], padded stride

    const int tid  = threadIdx.x;
    const int row0 = blockIdx.x * 64;

    {
        const float4* W4  = (const float4*)W;
        float4*       sW4 = (float4*)sW;
#pragma unroll
        for (int i = 0; i < 4; i++) sW4[tid + 256 * i] = W4[tid + 256 * i];
    }
#pragma unroll
    for (int i = 0; i < 4; i++) {
        int idx = tid + 256 * i;
        int r   = idx >> 4;
        int kk  = idx & 15;
        float4 v = make_float4(0.f, 0.f, 0.f, 0.f);
        if (row0 + r < n)
            v = ((const float4*)(x + (size_t)(row0 + r) * D_FEAT))[kk];
        *(float4*)&sx[r * 68 + kk * 4] = v;
    }
    __syncthreads();

    const int c4 = tid & 15;
    const int r0 = tid >> 4;

    float4 acc[4];
#pragma unroll
    for (int j = 0; j < 4; j++) acc[j] = make_float4(0.f, 0.f, 0.f, 0.f);

#pragma unroll 8
    for (int k = 0; k < 64; k++) {
        float4 w = *(const float4*)&sW[k * 64 + c4 * 4];
#pragma unroll
        for (int j = 0; j < 4; j++) {
            float xv = sx[(r0 + 16 * j) * 68 + k];
            acc[j].x += xv * w.x;
            acc[j].y += xv * w.y;
            acc[j].z += xv * w.z;
            acc[j].w += xv * w.w;
        }
    }

    float4 bb = ((const float4*)b)[c4];
#pragma unroll
    for (int j = 0; j < 4; j++) {
        int r = row0 + r0 + 16 * j;
        if (r < n) {
            float4 v;
            v.x = fmaxf(acc[j].x + bb.x, 0.f);
            v.y = fmaxf(acc[j].y + bb.y, 0.f);
            v.z = fmaxf(acc[j].z + bb.z, 0.f);
            v.w = fmaxf(acc[j].w + bb.w, 0.f);
            ((float4*)(g_y + (size_t)r * D_FEAT))[c4] = v;
        }
    }
}

// ---------------------------------------------------------------------------
// Edge scatter: out[dst] += y[src].
// R2-proven lane mapping (16 lanes/edge, lane q <-> float4 q: every LDG/RED
// wavefront covers 2 full rows, perfectly coalesced), but each thread now
// handles 4 independent edges (e, e+EQ, e+2EQ, e+3EQ) so the idx->gather
// dependent chain runs at MLP=4.
// ---------------------------------------------------------------------------
__global__ __launch_bounds__(256) void scatter_kernel(float* __restrict__ out,
                                                      int E, int EQ) {
    int t = blockIdx.x * blockDim.x + threadIdx.x;
    int e0 = t >> 4;
    if (e0 >= EQ) return;
    int q = t & 15;

    // Batch 1: independent index loads.
    int2 ed[4];
    bool valid[4];
#pragma unroll
    for (int j = 0; j < 4; j++) {
        int e = e0 + j * EQ;
        valid[j] = (e < E);
        ed[j] = valid[j] ? __ldg(&g_edge[e]) : make_int2(0, 0);
    }

    // Batch 2: independent gathers (one coalesced float4 per edge).
    float4 v[4];
#pragma unroll
    for (int j = 0; j < 4; j++)
        v[j] = __ldg((const float4*)(g_y + (size_t)ed[j].x * D_FEAT) + q);

    // Batch 3: vectorized reductions (fire-and-forget).
#pragma unroll
    for (int j = 0; j < 4; j++) {
        if (!valid[j]) continue;
        float* o = out + (size_t)ed[j].y * D_FEAT + (q << 2);
        asm volatile("red.global.add.v4.f32 [%0], {%1, %2, %3, %4};"
                     :: "l"(o), "f"(v[j].x), "f"(v[j].y), "f"(v[j].z), "f"(v[j].w)
                     : "memory");
    }
}

// ---------------------------------------------------------------------------
// Inputs: x [n*64 f32], edge_index [2*E int32/int64], W [64*64 f32], b [64].
// ---------------------------------------------------------------------------
extern "C" void kernel_launch(void* const* d_in, const int* in_sizes, int n_in,
                              void* d_out, int out_size) {
    const float* x   = (const float*)d_in[0];
    const void*  ei  = d_in[1];
    const float* W   = (const float*)d_in[2];
    const float* b   = (const float*)d_in[3];
    float*       out = (float*)d_out;

    int n = in_sizes[0] / D_FEAT;
    int E = in_sizes[1] / 2;

    detect_kernel<<<1, 256>>>((const int*)ei);
    prep_kernel<<<(E + 255) / 256, 256>>>(ei, E);

    int n4 = out_size / 4;
    zero_kernel<<<(n4 + 255) / 256, 256>>>((float4*)d_out, n4);
    mlp_kernel<<<(n + 63) / 64, 256>>>(x, W, b, n);

    int EQ = (E + 3) / 4;                       // edges per thread-slot
    long long total = (long long)EQ * 16;       // threads
    int grid = (int)((total + 255) / 256);
    scatter_kernel<<<grid, 256>>>(out, E, EQ);
}

// round 9
// speedup vs baseline: 2.2167x; 1.0086x over previous
#include <cuda_runtime.h>
#include <cuda_fp16.h>
#include <cstdint>

#define D_FEAT    64
#define MAX_NODES 50000
#define MAX_EDGES 800000

// Scratch (__device__ globals — no allocation allowed).
static __device__ __half g_y[(size_t)MAX_NODES * D_FEAT];  // relu(x W + b), fp16
static __device__ int2   g_edge[MAX_EDGES];                // packed (src, dst)
static __device__ int    g_is64;                           // edge_index dtype flag

// ---------------------------------------------------------------------------
// Detect index dtype: int64 indices < 2^31 have every odd 32-bit word == 0.
// ---------------------------------------------------------------------------
__global__ void detect_kernel(const int* __restrict__ ei_words) {
    __shared__ int any_nonzero;
    if (threadIdx.x == 0) any_nonzero = 0;
    __syncthreads();
    if (ei_words[2 * threadIdx.x + 1] != 0) atomicOr(&any_nonzero, 1);
    __syncthreads();
    if (threadIdx.x == 0) g_is64 = any_nonzero ? 0 : 1;
}

// ---------------------------------------------------------------------------
// Convert edge_index (int32 or int64, [2, E]) into packed int2 (src, dst).
// ---------------------------------------------------------------------------
__global__ __launch_bounds__(256) void prep_kernel(const void* __restrict__ ei, int E) {
    int e = blockIdx.x * blockDim.x + threadIdx.x;
    if (e >= E) return;
    int src, dst;
    if (g_is64) {
        const long long* p = (const long long*)ei;
        src = (int)__ldg(&p[e]);
        dst = (int)__ldg(&p[(size_t)E + e]);
    } else {
        const int* p = (const int*)ei;
        src = __ldg(&p[e]);
        dst = __ldg(&p[(size_t)E + e]);
    }
    g_edge[e] = make_int2(src, dst);
}

// ---------------------------------------------------------------------------
// Zero the output buffer (harness poisons it to 0xAA).
// ---------------------------------------------------------------------------
__global__ void zero_kernel(float4* __restrict__ out, int n4) {
    int i = blockIdx.x * blockDim.x + threadIdx.x;
    if (i < n4) out[i] = make_float4(0.f, 0.f, 0.f, 0.f);
}

// ---------------------------------------------------------------------------
// Per-node MLP: y = relu(x @ W + b), stored fp16.
// 256 thr / 64 rows per block. k-tiled by 4: per step 8 LDS.128 feed 64 FFMA
// (vs 5 LDS per 16 FFMA before) — fewer issue slots, 4x the ILP.
// ---------------------------------------------------------------------------
__global__ __launch_bounds__(256) void mlp_kernel(const float* __restrict__ x,
                                                  const float* __restrict__ W,
                                                  const float* __restrict__ b,
                                                  int n) {
    __shared__ float sW[64 * 64];   // [k][c]
    __shared__ float sx[64 * 68];   // [r][k], padded stride (68 % 16 row alignment ok)

    const int tid  = threadIdx.x;
    const int row0 = blockIdx.x * 64;

    {
        const float4* W4  = (const float4*)W;
        float4*       sW4 = (float4*)sW;
#pragma unroll
        for (int i = 0; i < 4; i++) sW4[tid + 256 * i] = W4[tid + 256 * i];
    }
#pragma unroll
    for (int i = 0; i < 4; i++) {
        int idx = tid + 256 * i;
        int r   = idx >> 4;
        int kk  = idx & 15;
        float4 v = make_float4(0.f, 0.f, 0.f, 0.f);
        if (row0 + r < n)
            v = ((const float4*)(x + (size_t)(row0 + r) * D_FEAT))[kk];
        *(float4*)&sx[r * 68 + kk * 4] = v;
    }
    __syncthreads();

    const int c4 = tid & 15;   // column group (4 cols)
    const int r0 = tid >> 4;   // row slot; rows r0 + 16j

    float4 acc[4];
#pragma unroll
    for (int j = 0; j < 4; j++) acc[j] = make_float4(0.f, 0.f, 0.f, 0.f);

#pragma unroll 4
    for (int k4 = 0; k4 < 16; k4++) {
        float4 xr[4];
#pragma unroll
        for (int j = 0; j < 4; j++)
            xr[j] = *(const float4*)&sx[(r0 + 16 * j) * 68 + k4 * 4];
        float4 w0 = *(const float4*)&sW[(k4 * 4 + 0) * 64 + c4 * 4];
        float4 w1 = *(const float4*)&sW[(k4 * 4 + 1) * 64 + c4 * 4];
        float4 w2 = *(const float4*)&sW[(k4 * 4 + 2) * 64 + c4 * 4];
        float4 w3 = *(const float4*)&sW[(k4 * 4 + 3) * 64 + c4 * 4];
#pragma unroll
        for (int j = 0; j < 4; j++) {
            acc[j].x += xr[j].x * w0.x + xr[j].y * w1.x + xr[j].z * w2.x + xr[j].w * w3.x;
            acc[j].y += xr[j].x * w0.y + xr[j].y * w1.y + xr[j].z * w2.y + xr[j].w * w3.y;
            acc[j].z += xr[j].x * w0.z + xr[j].y * w1.z + xr[j].z * w2.z + xr[j].w * w3.z;
            acc[j].w += xr[j].x * w0.w + xr[j].y * w1.w + xr[j].z * w2.w + xr[j].w * w3.w;
        }
    }

    float4 bb = ((const float4*)b)[c4];
#pragma unroll
    for (int j = 0; j < 4; j++) {
        int r = row0 + r0 + 16 * j;
        if (r < n) {
            __half2 h0 = __floats2half2_rn(fmaxf(acc[j].x + bb.x, 0.f),
                                           fmaxf(acc[j].y + bb.y, 0.f));
            __half2 h1 = __floats2half2_rn(fmaxf(acc[j].z + bb.z, 0.f),
                                           fmaxf(acc[j].w + bb.w, 0.f));
            uint2 pk;
            pk.x = *(const unsigned*)&h0;
            pk.y = *(const unsigned*)&h1;
            ((uint2*)(g_y + (size_t)r * D_FEAT))[c4] = pk;
        }
    }
}

// ---------------------------------------------------------------------------
// Edge scatter: out[dst] += y[src]  (fp16 gather, fp32 vectorized RED).
// 16 lanes/edge, lane q <-> halves [4q..4q+3] (uint2, 8B): a warp gather =
// 2 full rows x 128B, perfectly coalesced. 4 independent edges per thread
// (e, e+EQ, e+2EQ, e+3EQ) keep the idx->gather chain at MLP=4.
// ---------------------------------------------------------------------------
__global__ __launch_bounds__(256) void scatter_kernel(float* __restrict__ out,
                                                      int E, int EQ) {
    int t = blockIdx.x * blockDim.x + threadIdx.x;
    int e0 = t >> 4;
    if (e0 >= EQ) return;
    int q = t & 15;

    int2 ed[4];
    bool valid[4];
#pragma unroll
    for (int j = 0; j < 4; j++) {
        int e = e0 + j * EQ;
        valid[j] = (e < E);
        ed[j] = valid[j] ? __ldg(&g_edge[e]) : make_int2(0, 0);
    }

    uint2 hv[4];
#pragma unroll
    for (int j = 0; j < 4; j++)
        hv[j] = __ldg((const uint2*)(g_y + (size_t)ed[j].x * D_FEAT) + q);

#pragma unroll
    for (int j = 0; j < 4; j++) {
        if (!valid[j]) continue;
        float2 f0 = __half22float2(*(const __half2*)&hv[j].x);
        float2 f1 = __half22float2(*(const __half2*)&hv[j].y);
        float* o = out + (size_t)ed[j].y * D_FEAT + (q << 2);
        asm volatile("red.global.add.v4.f32 [%0], {%1, %2, %3, %4};"
                     :: "l"(o), "f"(f0.x), "f"(f0.y), "f"(f1.x), "f"(f1.y)
                     : "memory");
    }
}

// ---------------------------------------------------------------------------
// Inputs: x [n*64 f32], edge_index [2*E int32/int64], W [64*64 f32], b [64].
// ---------------------------------------------------------------------------
extern "C" void kernel_launch(void* const* d_in, const int* in_sizes, int n_in,
                              void* d_out, int out_size) {
    const float* x   = (const float*)d_in[0];
    const void*  ei  = d_in[1];
    const float* W   = (const float*)d_in[2];
    const float* b   = (const float*)d_in[3];
    float*       out = (float*)d_out;

    int n = in_sizes[0] / D_FEAT;
    int E = in_sizes[1] / 2;

    detect_kernel<<<1, 256>>>((const int*)ei);
    prep_kernel<<<(E + 255) / 256, 256>>>(ei, E);

    int n4 = out_size / 4;
    zero_kernel<<<(n4 + 255) / 256, 256>>>((float4*)d_out, n4);
    mlp_kernel<<<(n + 63) / 64, 256>>>(x, W, b, n);

    int EQ = (E + 3) / 4;
    long long total = (long long)EQ * 16;
    int grid = (int)((total + 255) / 256);
    scatter_kernel<<<grid, 256>>>(out, E, EQ);
}

// round 10
// speedup vs baseline: 2.7505x; 1.2408x over previous
#include <cuda_runtime.h>
#include <cuda_fp16.h>
#include <cstdint>

#define D_FEAT    64
#define MAX_NODES 50000
#define MAX_EDGES 800000

// Scratch (__device__ globals — no allocation allowed).
static __device__ __half g_y[(size_t)MAX_NODES * D_FEAT];     // relu(x W + b), fp16
static __device__ __half g_hout[(size_t)MAX_NODES * D_FEAT];  // fp16 accumulator
static __device__ int2   g_edge[MAX_EDGES];                   // packed (src, dst)
static __device__ int    g_is64;                              // edge_index dtype flag

// ---------------------------------------------------------------------------
// Detect index dtype: int64 indices < 2^31 have every odd 32-bit word == 0.
// ---------------------------------------------------------------------------
__global__ void detect_kernel(const int* __restrict__ ei_words) {
    __shared__ int any_nonzero;
    if (threadIdx.x == 0) any_nonzero = 0;
    __syncthreads();
    if (ei_words[2 * threadIdx.x + 1] != 0) atomicOr(&any_nonzero, 1);
    __syncthreads();
    if (threadIdx.x == 0) g_is64 = any_nonzero ? 0 : 1;
}

// ---------------------------------------------------------------------------
// Convert edge_index (int32 or int64, [2, E]) into packed int2 (src, dst).
// ---------------------------------------------------------------------------
__global__ __launch_bounds__(256) void prep_kernel(const void* __restrict__ ei, int E) {
    int e = blockIdx.x * blockDim.x + threadIdx.x;
    if (e >= E) return;
    int src, dst;
    if (g_is64) {
        const long long* p = (const long long*)ei;
        src = (int)__ldg(&p[e]);
        dst = (int)__ldg(&p[(size_t)E + e]);
    } else {
        const int* p = (const int*)ei;
        src = __ldg(&p[e]);
        dst = __ldg(&p[(size_t)E + e]);
    }
    g_edge[e] = make_int2(src, dst);
}

// ---------------------------------------------------------------------------
// Zero the fp16 accumulator (n*64 halves = n*8 uint4).
// ---------------------------------------------------------------------------
__global__ void zeroh_kernel(int n16) {
    int i = blockIdx.x * blockDim.x + threadIdx.x;
    if (i < n16) ((uint4*)g_hout)[i] = make_uint4(0u, 0u, 0u, 0u);
}

// ---------------------------------------------------------------------------
// Per-node MLP: y = relu(x @ W + b), stored fp16.
// ---------------------------------------------------------------------------
__global__ __launch_bounds__(256) void mlp_kernel(const float* __restrict__ x,
                                                  const float* __restrict__ W,
                                                  const float* __restrict__ b,
                                                  int n) {
    __shared__ float sW[64 * 64];   // [k][c]
    __shared__ float sx[64 * 68];   // [r][k], padded stride

    const int tid  = threadIdx.x;
    const int row0 = blockIdx.x * 64;

    {
        const float4* W4  = (const float4*)W;
        float4*       sW4 = (float4*)sW;
#pragma unroll
        for (int i = 0; i < 4; i++) sW4[tid + 256 * i] = W4[tid + 256 * i];
    }
#pragma unroll
    for (int i = 0; i < 4; i++) {
        int idx = tid + 256 * i;
        int r   = idx >> 4;
        int kk  = idx & 15;
        float4 v = make_float4(0.f, 0.f, 0.f, 0.f);
        if (row0 + r < n)
            v = ((const float4*)(x + (size_t)(row0 + r) * D_FEAT))[kk];
        *(float4*)&sx[r * 68 + kk * 4] = v;
    }
    __syncthreads();

    const int c4 = tid & 15;
    const int r0 = tid >> 4;

    float4 acc[4];
#pragma unroll
    for (int j = 0; j < 4; j++) acc[j] = make_float4(0.f, 0.f, 0.f, 0.f);

#pragma unroll 4
    for (int k4 = 0; k4 < 16; k4++) {
        float4 xr[4];
#pragma unroll
        for (int j = 0; j < 4; j++)
            xr[j] = *(const float4*)&sx[(r0 + 16 * j) * 68 + k4 * 4];
        float4 w0 = *(const float4*)&sW[(k4 * 4 + 0) * 64 + c4 * 4];
        float4 w1 = *(const float4*)&sW[(k4 * 4 + 1) * 64 + c4 * 4];
        float4 w2 = *(const float4*)&sW[(k4 * 4 + 2) * 64 + c4 * 4];
        float4 w3 = *(const float4*)&sW[(k4 * 4 + 3) * 64 + c4 * 4];
#pragma unroll
        for (int j = 0; j < 4; j++) {
            acc[j].x += xr[j].x * w0.x + xr[j].y * w1.x + xr[j].z * w2.x + xr[j].w * w3.x;
            acc[j].y += xr[j].x * w0.y + xr[j].y * w1.y + xr[j].z * w2.y + xr[j].w * w3.y;
            acc[j].z += xr[j].x * w0.z + xr[j].y * w1.z + xr[j].z * w2.z + xr[j].w * w3.z;
            acc[j].w += xr[j].x * w0.w + xr[j].y * w1.w + xr[j].z * w2.w + xr[j].w * w3.w;
        }
    }

    float4 bb = ((const float4*)b)[c4];
#pragma unroll
    for (int j = 0; j < 4; j++) {
        int r = row0 + r0 + 16 * j;
        if (r < n) {
            __half2 h0 = __floats2half2_rn(fmaxf(acc[j].x + bb.x, 0.f),
                                           fmaxf(acc[j].y + bb.y, 0.f));
            __half2 h1 = __floats2half2_rn(fmaxf(acc[j].z + bb.z, 0.f),
                                           fmaxf(acc[j].w + bb.w, 0.f));
            uint2 pk;
            pk.x = *(const unsigned*)&h0;
            pk.y = *(const unsigned*)&h1;
            ((uint2*)(g_y + (size_t)r * D_FEAT))[c4] = pk;
        }
    }
}

// ---------------------------------------------------------------------------
// Edge scatter: g_hout[dst] += y[src], all fp16.
// 8 lanes/edge, lane q <-> halves [8q..8q+7] (uint4, 16B): a warp covers 4
// full rows x 128B, perfectly coalesced. One red.v4.f16x2 per (thread, edge)
// covers 8 features -> atomic op count halved vs v4.f32.
// 4 independent edges per thread (e, e+EQ, e+2EQ, e+3EQ) keep MLP=4.
// ---------------------------------------------------------------------------
__global__ __launch_bounds__(256) void scatter_kernel(int E, int EQ) {
    int t = blockIdx.x * blockDim.x + threadIdx.x;
    int e0 = t >> 3;
    if (e0 >= EQ) return;
    int q = t & 7;

    int2 ed[4];
    bool valid[4];
#pragma unroll
    for (int j = 0; j < 4; j++) {
        int e = e0 + j * EQ;
        valid[j] = (e < E);
        ed[j] = valid[j] ? __ldg(&g_edge[e]) : make_int2(0, 0);
    }

    uint4 hv[4];
#pragma unroll
    for (int j = 0; j < 4; j++)
        hv[j] = __ldg((const uint4*)(g_y + (size_t)ed[j].x * D_FEAT) + q);

#pragma unroll
    for (int j = 0; j < 4; j++) {
        if (!valid[j]) continue;
        __half* o = g_hout + (size_t)ed[j].y * D_FEAT + (q << 3);
        asm volatile("red.global.add.noftz.v4.f16x2 [%0], {%1, %2, %3, %4};"
                     :: "l"(o), "r"(hv[j].x), "r"(hv[j].y), "r"(hv[j].z), "r"(hv[j].w)
                     : "memory");
    }
}

// ---------------------------------------------------------------------------
// Convert fp16 accumulator -> fp32 output. One thread per 8 halves.
// ---------------------------------------------------------------------------
__global__ __launch_bounds__(256) void convert_kernel(float* __restrict__ out, int n16) {
    int i = blockIdx.x * blockDim.x + threadIdx.x;
    if (i >= n16) return;
    uint4 h = ((const uint4*)g_hout)[i];
    float2 f0 = __half22float2(*(const __half2*)&h.x);
    float2 f1 = __half22float2(*(const __half2*)&h.y);
    float2 f2 = __half22float2(*(const __half2*)&h.z);
    float2 f3 = __half22float2(*(const __half2*)&h.w);
    float4* o = (float4*)out + (size_t)i * 2;
    o[0] = make_float4(f0.x, f0.y, f1.x, f1.y);
    o[1] = make_float4(f2.x, f2.y, f3.x, f3.y);
}

// ---------------------------------------------------------------------------
// Inputs: x [n*64 f32], edge_index [2*E int32/int64], W [64*64 f32], b [64].
// ---------------------------------------------------------------------------
extern "C" void kernel_launch(void* const* d_in, const int* in_sizes, int n_in,
                              void* d_out, int out_size) {
    const float* x   = (const float*)d_in[0];
    const void*  ei  = d_in[1];
    const float* W   = (const float*)d_in[2];
    const float* b   = (const float*)d_in[3];
    float*       out = (float*)d_out;

    int n = in_sizes[0] / D_FEAT;
    int E = in_sizes[1] / 2;

    detect_kernel<<<1, 256>>>((const int*)ei);
    prep_kernel<<<(E + 255) / 256, 256>>>(ei, E);

    int n16 = n * D_FEAT / 8;   // uint4 groups in the fp16 accumulator
    zeroh_kernel<<<(n16 + 255) / 256, 256>>>(n16);
    mlp_kernel<<<(n + 63) / 64, 256>>>(x, W, b, n);

    int EQ = (E + 3) / 4;
    long long total = (long long)EQ * 8;
    int grid = (int)((total + 255) / 256);
    scatter_kernel<<<grid, 256>>>(E, EQ);

    convert_kernel<<<(n16 + 255) / 256, 256>>>(out, n16);
}

// round 11
// speedup vs baseline: 2.7653x; 1.0054x over previous
#include <cuda_runtime.h>
#include <cuda_fp16.h>
#include <cstdint>

#define D_FEAT    64
#define MAX_NODES 50000
#define MAX_EDGES 800000

// Scratch (__device__ globals — no allocation allowed).
static __device__ __half g_y[(size_t)MAX_NODES * D_FEAT];     // relu(x W + b), fp16
static __device__ __half g_hout[(size_t)MAX_NODES * D_FEAT];  // fp16 accumulator
static __device__ int2   g_edge[MAX_EDGES];                   // packed (src, dst)
static __device__ int    g_is64;                              // edge_index dtype flag

// ---------------------------------------------------------------------------
// Detect index dtype: int64 indices < 2^31 have every odd 32-bit word == 0.
// ---------------------------------------------------------------------------
__global__ void detect_kernel(const int* __restrict__ ei_words) {
    __shared__ int any_nonzero;
    if (threadIdx.x == 0) any_nonzero = 0;
    __syncthreads();
    if (ei_words[2 * threadIdx.x + 1] != 0) atomicOr(&any_nonzero, 1);
    __syncthreads();
    if (threadIdx.x == 0) g_is64 = any_nonzero ? 0 : 1;
}

// ---------------------------------------------------------------------------
// Pack edge_index into int2 AND zero the fp16 accumulator (fused).
// ---------------------------------------------------------------------------
__global__ __launch_bounds__(256) void prep_kernel(const void* __restrict__ ei,
                                                   int E, int n16) {
    int t = blockIdx.x * blockDim.x + threadIdx.x;
    if (t < E) {
        int src, dst;
        if (g_is64) {
            const long long* p = (const long long*)ei;
            src = (int)__ldg(&p[t]);
            dst = (int)__ldg(&p[(size_t)E + t]);
        } else {
            const int* p = (const int*)ei;
            src = __ldg(&p[t]);
            dst = __ldg(&p[(size_t)E + t]);
        }
        g_edge[t] = make_int2(src, dst);
    }
    if (t < n16) ((uint4*)g_hout)[t] = make_uint4(0u, 0u, 0u, 0u);
}

// ---------------------------------------------------------------------------
// Per-node MLP: y = relu(x @ W + b), stored fp16.
// Packed-pair math: fma.rn.f32x2 accumulates (even-k, odd-k) partials.
//   x pairs come free from LDS.128 of k-major sx rows.
//   w pairs come free from pair-major transposed W: sWp[k2][2c+parity].
// Thread owns rows {r0+16j} and cols {c4+16cc}.
// Inner loop per k4: 4 LDS.128 + 8 LDS.64 + 32 FFMA2  (was 8 LDS.128 + 64 FFMA).
// ---------------------------------------------------------------------------
__global__ __launch_bounds__(256) void mlp_kernel(const float* __restrict__ x,
                                                  const float* __restrict__ W,
                                                  const float* __restrict__ b,
                                                  int n) {
    __shared__ float sWp[32 * 128];   // [k2][2c+par], 16KB
    __shared__ float sx[64 * 68];     // [r][k], padded stride, 17KB

    const int tid  = threadIdx.x;
    const int row0 = blockIdx.x * 64;

    // Fill sWp: W[k][c] -> sWp[k>>1][2c + (k&1)]
#pragma unroll
    for (int i = 0; i < 4; i++) {
        int idx = tid + 256 * i;          // 0..1023 over W's float4s
        int k   = idx >> 4;
        int kk  = idx & 15;
        float4 v = ((const float4*)W)[idx];
        float* dstrow = &sWp[(k >> 1) * 128 + (k & 1)];
        dstrow[2 * (4 * kk + 0)] = v.x;
        dstrow[2 * (4 * kk + 1)] = v.y;
        dstrow[2 * (4 * kk + 2)] = v.z;
        dstrow[2 * (4 * kk + 3)] = v.w;
    }
    // Fill sx
#pragma unroll
    for (int i = 0; i < 4; i++) {
        int idx = tid + 256 * i;
        int r   = idx >> 4;
        int kk  = idx & 15;
        float4 v = make_float4(0.f, 0.f, 0.f, 0.f);
        if (row0 + r < n)
            v = ((const float4*)(x + (size_t)(row0 + r) * D_FEAT))[kk];
        *(float4*)&sx[r * 68 + kk * 4] = v;
    }
    __syncthreads();

    const int c4 = tid & 15;   // cols c4 + 16*cc
    const int r0 = tid >> 4;   // rows r0 + 16*j

    unsigned long long acc[4][4];
#pragma unroll
    for (int j = 0; j < 4; j++)
#pragma unroll
        for (int cc = 0; cc < 4; cc++) acc[j][cc] = 0ULL;

#pragma unroll 4
    for (int k4 = 0; k4 < 16; k4++) {
        // x: 4 rows, each LDS.128 = two f32x2 pairs (k4*4+0/1, k4*4+2/3)
        ulonglong2 xr[4];
#pragma unroll
        for (int j = 0; j < 4; j++)
            xr[j] = *(const ulonglong2*)&sx[(r0 + 16 * j) * 68 + k4 * 4];

#pragma unroll
        for (int sub = 0; sub < 2; sub++) {
            int k2 = k4 * 2 + sub;
            unsigned long long wp[4];
#pragma unroll
            for (int cc = 0; cc < 4; cc++)
                wp[cc] = *(const unsigned long long*)
                         &sWp[k2 * 128 + 2 * (c4 + 16 * cc)];
#pragma unroll
            for (int j = 0; j < 4; j++) {
                unsigned long long xp = sub ? xr[j].y : xr[j].x;
#pragma unroll
                for (int cc = 0; cc < 4; cc++)
                    asm("fma.rn.f32x2 %0, %1, %2, %0;"
                        : "+l"(acc[j][cc]) : "l"(xp), "l"(wp[cc]));
            }
        }
    }

    // Fold pairs, add bias, relu; stage fp32 results into sx for coalesced store.
    float bv[4];
#pragma unroll
    for (int cc = 0; cc < 4; cc++) bv[cc] = __ldg(&b[c4 + 16 * cc]);

    __syncthreads();   // done reading sx; reuse as staging
#pragma unroll
    for (int j = 0; j < 4; j++) {
#pragma unroll
        for (int cc = 0; cc < 4; cc++) {
            unsigned long long a = acc[j][cc];
            float lo = __uint_as_float((unsigned)(a & 0xFFFFFFFFu));
            float hi = __uint_as_float((unsigned)(a >> 32));
            float s  = fmaxf(lo + hi + bv[cc], 0.f);
            sx[(r0 + 16 * j) * 68 + (c4 + 16 * cc)] = s;
        }
    }
    __syncthreads();

    // Coalesced fp16 store (proven pattern).
#pragma unroll
    for (int i = 0; i < 4; i++) {
        int idx = tid + 256 * i;
        int r   = idx >> 4;
        int kk  = idx & 15;
        if (row0 + r < n) {
            float4 v = *(const float4*)&sx[r * 68 + kk * 4];
            __half2 h0 = __floats2half2_rn(v.x, v.y);
            __half2 h1 = __floats2half2_rn(v.z, v.w);
            uint2 pk;
            pk.x = *(const unsigned*)&h0;
            pk.y = *(const unsigned*)&h1;
            ((uint2*)(g_y + (size_t)(row0 + r) * D_FEAT))[kk] = pk;
        }
    }
}

// ---------------------------------------------------------------------------
// Edge scatter: g_hout[dst] += y[src], all fp16.
// 8 lanes/edge (lane q <-> uint4 = 8 halves; warp = 4 rows x 128B coalesced),
// 4 independent edges/thread (MLP=4), red.v4.f16x2 covers 8 feats per op.
// ---------------------------------------------------------------------------
__global__ __launch_bounds__(256) void scatter_kernel(int E, int EQ) {
    int t = blockIdx.x * blockDim.x + threadIdx.x;
    int e0 = t >> 3;
    if (e0 >= EQ) return;
    int q = t & 7;

    int2 ed[4];
    bool valid[4];
#pragma unroll
    for (int j = 0; j < 4; j++) {
        int e = e0 + j * EQ;
        valid[j] = (e < E);
        ed[j] = valid[j] ? __ldg(&g_edge[e]) : make_int2(0, 0);
    }

    uint4 hv[4];
#pragma unroll
    for (int j = 0; j < 4; j++)
        hv[j] = __ldg((const uint4*)(g_y + (size_t)ed[j].x * D_FEAT) + q);

#pragma unroll
    for (int j = 0; j < 4; j++) {
        if (!valid[j]) continue;
        __half* o = g_hout + (size_t)ed[j].y * D_FEAT + (q << 3);
        asm volatile("red.global.add.noftz.v4.f16x2 [%0], {%1, %2, %3, %4};"
                     :: "l"(o), "r"(hv[j].x), "r"(hv[j].y), "r"(hv[j].z), "r"(hv[j].w)
                     : "memory");
    }
}

// ---------------------------------------------------------------------------
// Convert fp16 accumulator -> fp32 output. One thread per 8 halves.
// ---------------------------------------------------------------------------
__global__ __launch_bounds__(256) void convert_kernel(float* __restrict__ out, int n16) {
    int i = blockIdx.x * blockDim.x + threadIdx.x;
    if (i >= n16) return;
    uint4 h = ((const uint4*)g_hout)[i];
    float2 f0 = __half22float2(*(const __half2*)&h.x);
    float2 f1 = __half22float2(*(const __half2*)&h.y);
    float2 f2 = __half22float2(*(const __half2*)&h.z);
    float2 f3 = __half22float2(*(const __half2*)&h.w);
    float4* o = (float4*)out + (size_t)i * 2;
    o[0] = make_float4(f0.x, f0.y, f1.x, f1.y);
    o[1] = make_float4(f2.x, f2.y, f3.x, f3.y);
}

// ---------------------------------------------------------------------------
// Inputs: x [n*64 f32], edge_index [2*E int32/int64], W [64*64 f32], b [64].
// ---------------------------------------------------------------------------
extern "C" void kernel_launch(void* const* d_in, const int* in_sizes, int n_in,
                              void* d_out, int out_size) {
    const float* x   = (const float*)d_in[0];
    const void*  ei  = d_in[1];
    const float* W   = (const float*)d_in[2];
    const float* b   = (const float*)d_in[3];
    float*       out = (float*)d_out;

    int n = in_sizes[0] / D_FEAT;
    int E = in_sizes[1] / 2;
    int n16 = n * D_FEAT / 8;   // uint4 groups in the fp16 accumulator

    detect_kernel<<<1, 256>>>((const int*)ei);

    int prep_elems = (E > n16) ? E : n16;
    prep_kernel<<<(prep_elems + 255) / 256, 256>>>(ei, E, n16);

    mlp_kernel<<<(n + 63) / 64, 256>>>(x, W, b, n);

    int EQ = (E + 3) / 4;
    long long total = (long long)EQ * 8;
    int grid = (int)((total + 255) / 256);
    scatter_kernel<<<grid, 256>>>(E, EQ);

    convert_kernel<<<(n16 + 255) / 256, 256>>>(out, n16);
}